// round 2
// baseline (speedup 1.0000x reference)
#include <cuda_runtime.h>
#include <cuda_bf16.h>

// Problem constants
#define BATCH 4
#define SEQ   2048
#define EMBD  1024
#define NHEAD 16
#define HDIM  64
#define QKV_N (3*EMBD)

// Scratch (device globals: allocation-free, graph-capture safe)
__device__ float g_qkv[(size_t)BATCH * SEQ * QKV_N];   // [B,T,3C]
__device__ float g_attn[(size_t)BATCH * SEQ * EMBD];   // [B,T,C]

// ---------------------------------------------------------------------------
// Tiled SGEMM with fused bias: C[M,N] = A[M,K] @ B[K,N] + bias[N]
// BM=128, BN=128, BK=8, 256 threads, 8x8 per thread.
// ---------------------------------------------------------------------------
#define BM 128
#define BN 128
#define BK 8
#define TM 8
#define TN 8

__global__ __launch_bounds__(256) void sgemm_bias(
    const float* __restrict__ A, const float* __restrict__ B,
    const float* __restrict__ bias, float* __restrict__ C,
    int M, int N, int K)
{
    __shared__ float As[BK][BM];
    __shared__ float Bs[BK][BN];

    const int tid  = threadIdx.x;
    const int brow = blockIdx.y;   // M tile
    const int bcol = blockIdx.x;   // N tile

    const float* Ab = A + (size_t)brow * BM * K;
    const float* Bb = B + (size_t)bcol * BN;

    // A tile load mapping: 128 rows x 8 cols, float4 per thread
    const int arow = tid >> 1;            // 0..127
    const int acol = (tid & 1) * 4;       // 0 or 4
    // B tile load mapping: 8 rows x 128 cols, float4 per thread
    const int brw = tid >> 5;             // 0..7
    const int bcl = (tid & 31) * 4;       // 0..124

    const int ty = tid >> 4;              // 0..15
    const int tx = tid & 15;              // 0..15

    float acc[TM][TN];
    #pragma unroll
    for (int i = 0; i < TM; i++)
        #pragma unroll
        for (int j = 0; j < TN; j++) acc[i][j] = 0.f;

    for (int k0 = 0; k0 < K; k0 += BK) {
        float4 av = *(const float4*)(Ab + (size_t)arow * K + k0 + acol);
        As[acol + 0][arow] = av.x;
        As[acol + 1][arow] = av.y;
        As[acol + 2][arow] = av.z;
        As[acol + 3][arow] = av.w;
        float4 bv = *(const float4*)(Bb + (size_t)(k0 + brw) * N + bcl);
        *(float4*)&Bs[brw][bcl] = bv;
        __syncthreads();

        #pragma unroll
        for (int kk = 0; kk < BK; kk++) {
            float ra[TM], rb[TN];
            float4 a0 = *(const float4*)&As[kk][ty * TM];
            float4 a1 = *(const float4*)&As[kk][ty * TM + 4];
            ra[0]=a0.x; ra[1]=a0.y; ra[2]=a0.z; ra[3]=a0.w;
            ra[4]=a1.x; ra[5]=a1.y; ra[6]=a1.z; ra[7]=a1.w;
            float4 b0 = *(const float4*)&Bs[kk][tx * TN];
            float4 b1 = *(const float4*)&Bs[kk][tx * TN + 4];
            rb[0]=b0.x; rb[1]=b0.y; rb[2]=b0.z; rb[3]=b0.w;
            rb[4]=b1.x; rb[5]=b1.y; rb[6]=b1.z; rb[7]=b1.w;
            #pragma unroll
            for (int i = 0; i < TM; i++)
                #pragma unroll
                for (int j = 0; j < TN; j++)
                    acc[i][j] += ra[i] * rb[j];
        }
        __syncthreads();
    }

    // Write with bias
    #pragma unroll
    for (int i = 0; i < TM; i++) {
        const int r = brow * BM + ty * TM + i;
        #pragma unroll
        for (int j = 0; j < TN; j += 4) {
            const int c = bcol * BN + tx * TN + j;
            float4 o;
            o.x = acc[i][j + 0] + bias[c + 0];
            o.y = acc[i][j + 1] + bias[c + 1];
            o.z = acc[i][j + 2] + bias[c + 2];
            o.w = acc[i][j + 3] + bias[c + 3];
            *(float4*)(C + (size_t)r * N + c) = o;
        }
    }
}

// ---------------------------------------------------------------------------
// Flash attention (causal), fp32. 1 thread = 1 query row.
// Block: 64 threads, handles 64 query rows of one (b,h).
// K tiles of 64 loaded to smem; S stashed per tile in smem (conflict-free).
// smem = 3 * 64*64*4 = 48 KB exactly -> 4 CTAs/SM.
// ---------------------------------------------------------------------------
#define AT 64

__global__ __launch_bounds__(64) void flash_attn(
    const float* __restrict__ qkv, float* __restrict__ out)
{
    __shared__ float Ks[AT][HDIM];
    __shared__ float Vs[AT][HDIM];
    __shared__ float Ss[AT][AT];   // Ss[j][tid] — fast index = tid -> conflict-free

    const int tid = threadIdx.x;                 // 0..63 = query row in tile
    const int bh  = blockIdx.y;
    const int b   = bh >> 4;
    const int h   = bh & (NHEAD - 1);
    // heavy blocks (more K tiles) first to shrink the tail wave
    const int qblk = (gridDim.x - 1) - blockIdx.x;
    const int q0   = qblk * AT;
    const int tq   = q0 + tid;
    const float scale = 0.125f;                  // 1/sqrt(64)

    // Q row -> registers
    const float* qptr = qkv + ((size_t)(b * SEQ + tq)) * QKV_N + h * HDIM;
    float qreg[HDIM];
    #pragma unroll
    for (int d = 0; d < HDIM; d += 4) {
        float4 v = *(const float4*)(qptr + d);
        qreg[d] = v.x; qreg[d+1] = v.y; qreg[d+2] = v.z; qreg[d+3] = v.w;
    }

    float m = -1e30f, l = 0.f;
    float accd[HDIM];
    #pragma unroll
    for (int d = 0; d < HDIM; d++) accd[d] = 0.f;

    const int ntiles = qblk + 1;                 // causal: only tiles <= own tile
    for (int t = 0; t < ntiles; t++) {
        const int k0 = t * AT;
        // cooperative load of K,V tile (each thread loads its own row)
        {
            const float* kptr = qkv + ((size_t)(b * SEQ + k0 + tid)) * QKV_N + EMBD + h * HDIM;
            const float* vptr = kptr + EMBD;
            #pragma unroll
            for (int d = 0; d < HDIM; d += 4) {
                *(float4*)&Ks[tid][d] = *(const float4*)(kptr + d);
                *(float4*)&Vs[tid][d] = *(const float4*)(vptr + d);
            }
        }
        __syncthreads();

        // pass A: scores + tile max
        float mt = -1e30f;
        #pragma unroll 2
        for (int j = 0; j < AT; j++) {
            float s = 0.f;
            #pragma unroll
            for (int d = 0; d < HDIM; d++) s += qreg[d] * Ks[j][d];
            s *= scale;
            if (k0 + j > tq) s = -1e30f;         // causal mask
            Ss[j][tid] = s;
            mt = fmaxf(mt, s);
        }

        const float newm = fmaxf(m, mt);
        const float corr = __expf(m - newm);
        l *= corr;
        #pragma unroll
        for (int d = 0; d < HDIM; d++) accd[d] *= corr;

        // pass B: exp + PV accumulate
        #pragma unroll 2
        for (int j = 0; j < AT; j++) {
            const float p = __expf(Ss[j][tid] - newm);
            l += p;
            #pragma unroll
            for (int d = 0; d < HDIM; d++) accd[d] += p * Vs[j][d];
        }
        m = newm;
        __syncthreads();
    }

    const float inv = 1.f / l;
    float* optr = out + ((size_t)(b * SEQ + tq)) * EMBD + h * HDIM;
    #pragma unroll
    for (int d = 0; d < HDIM; d += 4) {
        float4 v;
        v.x = accd[d]   * inv;
        v.y = accd[d+1] * inv;
        v.z = accd[d+2] * inv;
        v.w = accd[d+3] * inv;
        *(float4*)(optr + d) = v;
    }
}

// ---------------------------------------------------------------------------
// Launch
// ---------------------------------------------------------------------------
extern "C" void kernel_launch(void* const* d_in, const int* in_sizes, int n_in,
                              void* d_out, int out_size)
{
    const float* x     = (const float*)d_in[0];   // [B,T,C]
    const float* W_qkv = (const float*)d_in[1];   // [C,3C]
    const float* b_qkv = (const float*)d_in[2];   // [3C]
    const float* W_out = (const float*)d_in[3];   // [C,C]
    const float* b_out = (const float*)d_in[4];   // [C]
    float* out = (float*)d_out;

    float* qkv;  cudaGetSymbolAddress((void**)&qkv,  g_qkv);
    float* attn; cudaGetSymbolAddress((void**)&attn, g_attn);

    const int M = BATCH * SEQ;   // 8192

    // 1) QKV projection: [8192,1024] @ [1024,3072] + b
    {
        dim3 grid(QKV_N / BN, M / BM);
        sgemm_bias<<<grid, 256>>>(x, W_qkv, b_qkv, qkv, M, QKV_N, EMBD);
    }
    // 2) Flash attention
    {
        dim3 grid(SEQ / AT, BATCH * NHEAD);
        flash_attn<<<grid, AT>>>(qkv, attn);
    }
    // 3) Output projection: [8192,1024] @ [1024,1024] + b
    {
        dim3 grid(EMBD / BN, M / BM);
        sgemm_bias<<<grid, 256>>>(attn, W_out, b_out, out, M, EMBD, EMBD);
    }
}

// round 3
// speedup vs baseline: 1.3293x; 1.3293x over previous
#include <cuda_runtime.h>
#include <cuda_bf16.h>

// Problem constants
#define BATCH 4
#define SEQ   2048
#define EMBD  1024
#define NHEAD 16
#define HDIM  64
#define QKV_N (3*EMBD)

typedef __nv_bfloat16 bf16;

// ---------------------------------------------------------------------------
// Scratch (device globals: allocation-free, graph-capture safe)
// ---------------------------------------------------------------------------
__device__ float g_qkv[(size_t)BATCH * SEQ * QKV_N];    // [B,T,3C] fp32
__device__ float g_attn[(size_t)BATCH * SEQ * EMBD];    // [B,T,C]  fp32
// bf16 hi/lo splits
__device__ bf16 g_xh[(size_t)BATCH * SEQ * EMBD];
__device__ bf16 g_xl[(size_t)BATCH * SEQ * EMBD];
__device__ bf16 g_ah[(size_t)BATCH * SEQ * EMBD];
__device__ bf16 g_al[(size_t)BATCH * SEQ * EMBD];
__device__ bf16 g_wqh[(size_t)EMBD * QKV_N];
__device__ bf16 g_wql[(size_t)EMBD * QKV_N];
__device__ bf16 g_woh[(size_t)EMBD * EMBD];
__device__ bf16 g_wol[(size_t)EMBD * EMBD];

// ---------------------------------------------------------------------------
// fp32 -> (bf16 hi, bf16 lo) split, vectorized x4
// ---------------------------------------------------------------------------
__global__ __launch_bounds__(256) void split_bf16x4(
    const float4* __restrict__ in, uint2* __restrict__ hi, uint2* __restrict__ lo, int n4)
{
    int i = blockIdx.x * blockDim.x + threadIdx.x;
    if (i >= n4) return;
    float4 v = in[i];
    float a[4] = {v.x, v.y, v.z, v.w};
    unsigned short h[4], l[4];
#pragma unroll
    for (int j = 0; j < 4; j++) {
        bf16 hb = __float2bfloat16_rn(a[j]);
        float r  = a[j] - __bfloat162float(hb);
        bf16 lb = __float2bfloat16_rn(r);
        h[j] = __bfloat16_as_ushort(hb);
        l[j] = __bfloat16_as_ushort(lb);
    }
    uint2 ho, loo;
    ho.x  = (unsigned)h[0] | ((unsigned)h[1] << 16);
    ho.y  = (unsigned)h[2] | ((unsigned)h[3] << 16);
    loo.x = (unsigned)l[0] | ((unsigned)l[1] << 16);
    loo.y = (unsigned)l[2] | ((unsigned)l[3] << 16);
    hi[i] = ho;
    lo[i] = loo;
}

// ---------------------------------------------------------------------------
// Tensor-core GEMM, bf16x3 emulated fp32:
//   C[M,N] = Ah@Bh + Ah@Bl + Al@Bh + bias
// A: [M,K] row-major (hi/lo), B: [K,N] row-major (hi/lo).
// Tile 128x128x32, 256 threads (8 warps, 2x4 warp grid, 64x32 per warp),
// cp.async double buffering, ldmatrix fragments, mma.sync m16n8k16.
// ---------------------------------------------------------------------------
#define GBM 128
#define GBN 128
#define GBK 32
#define APITCH 40    // 32 + 8 pad (bf16 elems); row stride 80B -> conflict-free
#define BPITCH 136   // 128 + 8 pad; row stride 272B -> conflict-free
#define ASZ (128*APITCH)
#define BSZ (32*BPITCH)

__device__ __forceinline__ unsigned sptr(const void* p) {
    return (unsigned)__cvta_generic_to_shared(p);
}
__device__ __forceinline__ void cpa16(unsigned s, const void* g) {
    asm volatile("cp.async.cg.shared.global [%0], [%1], 16;\n" :: "r"(s), "l"(g));
}
__device__ __forceinline__ void ldsm4(unsigned* r, unsigned a) {
    asm volatile("ldmatrix.sync.aligned.m8n8.x4.shared.b16 {%0,%1,%2,%3},[%4];"
                 : "=r"(r[0]), "=r"(r[1]), "=r"(r[2]), "=r"(r[3]) : "r"(a));
}
__device__ __forceinline__ void ldsm4t(unsigned* r, unsigned a) {
    asm volatile("ldmatrix.sync.aligned.m8n8.x4.trans.shared.b16 {%0,%1,%2,%3},[%4];"
                 : "=r"(r[0]), "=r"(r[1]), "=r"(r[2]), "=r"(r[3]) : "r"(a));
}
__device__ __forceinline__ void mma16816(float* d, const unsigned* a, const unsigned* b) {
    asm volatile(
        "mma.sync.aligned.m16n8k16.row.col.f32.bf16.bf16.f32 "
        "{%0,%1,%2,%3},{%4,%5,%6,%7},{%8,%9},{%0,%1,%2,%3};"
        : "+f"(d[0]), "+f"(d[1]), "+f"(d[2]), "+f"(d[3])
        : "r"(a[0]), "r"(a[1]), "r"(a[2]), "r"(a[3]), "r"(b[0]), "r"(b[1]));
}

__global__ __launch_bounds__(256, 1) void gemm_bf16x3(
    const bf16* __restrict__ Agh, const bf16* __restrict__ Agl,
    const bf16* __restrict__ Bgh, const bf16* __restrict__ Bgl,
    const float* __restrict__ bias, float* __restrict__ C,
    int M, int N, int K)
{
    extern __shared__ char smem[];
    bf16* sAh = (bf16*)smem;             // [2][ASZ]
    bf16* sAl = sAh + 2 * ASZ;
    bf16* sBh = sAl + 2 * ASZ;           // [2][BSZ]
    bf16* sBl = sBh + 2 * BSZ;

    const int tid  = threadIdx.x;
    const int lane = tid & 31;
    const int warp = tid >> 5;
    const int bm   = blockIdx.y * GBM;
    const int bn   = blockIdx.x * GBN;
    const int wm   = (warp & 1) * 64;
    const int wn   = (warp >> 1) * 32;

    float acc[4][4][4];
#pragma unroll
    for (int mi = 0; mi < 4; mi++)
#pragma unroll
        for (int n = 0; n < 4; n++)
#pragma unroll
            for (int e = 0; e < 4; e++) acc[mi][n][e] = 0.f;

    auto prefetch = [&](int st, int k0) {
        const bf16* ah = Agh + (size_t)bm * K + k0;
        const bf16* al = Agl + (size_t)bm * K + k0;
#pragma unroll
        for (int i = 0; i < 2; i++) {
            int idx = tid + i * 256;
            int r = idx >> 2, c = (idx & 3) * 8;
            cpa16(sptr(&sAh[st * ASZ + r * APITCH + c]), ah + (size_t)r * K + c);
            cpa16(sptr(&sAl[st * ASZ + r * APITCH + c]), al + (size_t)r * K + c);
        }
        const bf16* bh = Bgh + (size_t)k0 * N + bn;
        const bf16* bl = Bgl + (size_t)k0 * N + bn;
#pragma unroll
        for (int i = 0; i < 2; i++) {
            int idx = tid + i * 256;
            int r = idx >> 4, c = (idx & 15) * 8;
            cpa16(sptr(&sBh[st * BSZ + r * BPITCH + c]), bh + (size_t)r * N + c);
            cpa16(sptr(&sBl[st * BSZ + r * BPITCH + c]), bl + (size_t)r * N + c);
        }
        asm volatile("cp.async.commit_group;");
    };

    const int NIT = K / GBK;
    prefetch(0, 0);
    for (int it = 0; it < NIT; it++) {
        if (it + 1 < NIT) {
            prefetch((it + 1) & 1, (it + 1) * GBK);
            asm volatile("cp.async.wait_group 1;");
        } else {
            asm volatile("cp.async.wait_group 0;");
        }
        __syncthreads();
        const int st = it & 1;

#pragma unroll
        for (int kk = 0; kk < GBK; kk += 16) {
            unsigned ah[4][4], al[4][4], bh[2][4], bl[2][4];
#pragma unroll
            for (int mi = 0; mi < 4; mi++) {
                int row = wm + mi * 16 + (lane & 15);
                int col = kk + (lane >> 4) * 8;
                ldsm4(ah[mi], sptr(&sAh[st * ASZ + row * APITCH + col]));
                ldsm4(al[mi], sptr(&sAl[st * ASZ + row * APITCH + col]));
            }
#pragma unroll
            for (int nj = 0; nj < 2; nj++) {
                int row = kk + (lane & 15);
                int col = wn + nj * 16 + (lane >> 4) * 8;
                ldsm4t(bh[nj], sptr(&sBh[st * BSZ + row * BPITCH + col]));
                ldsm4t(bl[nj], sptr(&sBl[st * BSZ + row * BPITCH + col]));
            }
#pragma unroll
            for (int mi = 0; mi < 4; mi++)
#pragma unroll
                for (int nj = 0; nj < 2; nj++)
#pragma unroll
                    for (int sub = 0; sub < 2; sub++) {
                        int n = nj * 2 + sub;
                        mma16816(acc[mi][n], ah[mi], &bh[nj][sub * 2]);
                        mma16816(acc[mi][n], ah[mi], &bl[nj][sub * 2]);
                        mma16816(acc[mi][n], al[mi], &bh[nj][sub * 2]);
                    }
        }
        __syncthreads();
    }

    // Epilogue: m16n8 accumulator layout: c0,c1 -> (lane/4, (lane%4)*2), c2,c3 -> +8 rows
#pragma unroll
    for (int mi = 0; mi < 4; mi++) {
        int r0 = bm + wm + mi * 16 + (lane >> 2);
#pragma unroll
        for (int n = 0; n < 4; n++) {
            int c0 = bn + wn + n * 8 + (lane & 3) * 2;
            float2 bv = *(const float2*)(bias + c0);
            float2 o0 = {acc[mi][n][0] + bv.x, acc[mi][n][1] + bv.y};
            float2 o1 = {acc[mi][n][2] + bv.x, acc[mi][n][3] + bv.y};
            *(float2*)(C + (size_t)r0 * N + c0) = o0;
            *(float2*)(C + (size_t)(r0 + 8) * N + c0) = o1;
        }
    }
}

// ---------------------------------------------------------------------------
// Flash attention (causal), fp32. 1 thread = 1 query row (unchanged; next
// round moves this to tensor cores).
// ---------------------------------------------------------------------------
#define AT 64

__global__ __launch_bounds__(64) void flash_attn(
    const float* __restrict__ qkv, float* __restrict__ out)
{
    __shared__ float Ks[AT][HDIM];
    __shared__ float Vs[AT][HDIM];
    __shared__ float Ss[AT][AT];

    const int tid = threadIdx.x;
    const int bh  = blockIdx.y;
    const int b   = bh >> 4;
    const int h   = bh & (NHEAD - 1);
    const int qblk = (gridDim.x - 1) - blockIdx.x;   // heavy blocks first
    const int tq   = qblk * AT + tid;
    const float scale = 0.125f;

    const float* qptr = qkv + ((size_t)(b * SEQ + tq)) * QKV_N + h * HDIM;
    float qreg[HDIM];
#pragma unroll
    for (int d = 0; d < HDIM; d += 4) {
        float4 v = *(const float4*)(qptr + d);
        qreg[d] = v.x; qreg[d+1] = v.y; qreg[d+2] = v.z; qreg[d+3] = v.w;
    }

    float m = -1e30f, l = 0.f;
    float accd[HDIM];
#pragma unroll
    for (int d = 0; d < HDIM; d++) accd[d] = 0.f;

    const int ntiles = qblk + 1;
    for (int t = 0; t < ntiles; t++) {
        const int k0 = t * AT;
        {
            const float* kptr = qkv + ((size_t)(b * SEQ + k0 + tid)) * QKV_N + EMBD + h * HDIM;
            const float* vptr = kptr + EMBD;
#pragma unroll
            for (int d = 0; d < HDIM; d += 4) {
                *(float4*)&Ks[tid][d] = *(const float4*)(kptr + d);
                *(float4*)&Vs[tid][d] = *(const float4*)(vptr + d);
            }
        }
        __syncthreads();

        float mt = -1e30f;
#pragma unroll 2
        for (int j = 0; j < AT; j++) {
            float s = 0.f;
#pragma unroll
            for (int d = 0; d < HDIM; d++) s += qreg[d] * Ks[j][d];
            s *= scale;
            if (k0 + j > tq) s = -1e30f;
            Ss[j][tid] = s;
            mt = fmaxf(mt, s);
        }

        const float newm = fmaxf(m, mt);
        const float corr = __expf(m - newm);
        l *= corr;
#pragma unroll
        for (int d = 0; d < HDIM; d++) accd[d] *= corr;

#pragma unroll 2
        for (int j = 0; j < AT; j++) {
            const float p = __expf(Ss[j][tid] - newm);
            l += p;
#pragma unroll
            for (int d = 0; d < HDIM; d++) accd[d] += p * Vs[j][d];
        }
        m = newm;
        __syncthreads();
    }

    const float inv = 1.f / l;
    float* optr = out + ((size_t)(b * SEQ + tq)) * EMBD + h * HDIM;
#pragma unroll
    for (int d = 0; d < HDIM; d += 4) {
        float4 v;
        v.x = accd[d]   * inv;
        v.y = accd[d+1] * inv;
        v.z = accd[d+2] * inv;
        v.w = accd[d+3] * inv;
        *(float4*)(optr + d) = v;
    }
}

// ---------------------------------------------------------------------------
// Launch
// ---------------------------------------------------------------------------
extern "C" void kernel_launch(void* const* d_in, const int* in_sizes, int n_in,
                              void* d_out, int out_size)
{
    const float* x     = (const float*)d_in[0];
    const float* W_qkv = (const float*)d_in[1];
    const float* b_qkv = (const float*)d_in[2];
    const float* W_out = (const float*)d_in[3];
    const float* b_out = (const float*)d_in[4];
    float* out = (float*)d_out;

    float *qkv, *attn;
    bf16 *xh, *xl, *ah, *al, *wqh, *wql, *woh, *wol;
    cudaGetSymbolAddress((void**)&qkv,  g_qkv);
    cudaGetSymbolAddress((void**)&attn, g_attn);
    cudaGetSymbolAddress((void**)&xh,  g_xh);
    cudaGetSymbolAddress((void**)&xl,  g_xl);
    cudaGetSymbolAddress((void**)&ah,  g_ah);
    cudaGetSymbolAddress((void**)&al,  g_al);
    cudaGetSymbolAddress((void**)&wqh, g_wqh);
    cudaGetSymbolAddress((void**)&wql, g_wql);
    cudaGetSymbolAddress((void**)&woh, g_woh);
    cudaGetSymbolAddress((void**)&wol, g_wol);

    const int M = BATCH * SEQ;                       // 8192
    const int SMEM_GEMM = (2*ASZ + 2*ASZ + 2*BSZ + 2*BSZ) * (int)sizeof(bf16); // 75776
    static_assert((2*ASZ*2 + 2*ASZ*2 + 2*BSZ*2 + 2*BSZ*2) == 75776, "smem size");
    cudaFuncSetAttribute(gemm_bf16x3, cudaFuncAttributeMaxDynamicSharedMemorySize, SMEM_GEMM);

    // 1) split x and W_qkv into bf16 hi/lo
    {
        int n4 = M * EMBD / 4;
        split_bf16x4<<<(n4 + 255) / 256, 256>>>((const float4*)x, (uint2*)xh, (uint2*)xl, n4);
        n4 = EMBD * QKV_N / 4;
        split_bf16x4<<<(n4 + 255) / 256, 256>>>((const float4*)W_qkv, (uint2*)wqh, (uint2*)wql, n4);
    }
    // 2) QKV projection (tensor cores)
    {
        dim3 grid(QKV_N / GBN, M / GBM);
        gemm_bf16x3<<<grid, 256, SMEM_GEMM>>>(xh, xl, wqh, wql, b_qkv, qkv, M, QKV_N, EMBD);
    }
    // 3) Flash attention
    {
        dim3 grid(SEQ / AT, BATCH * NHEAD);
        flash_attn<<<grid, AT>>>(qkv, attn);
    }
    // 4) split attn and W_out
    {
        int n4 = M * EMBD / 4;
        split_bf16x4<<<(n4 + 255) / 256, 256>>>((const float4*)attn, (uint2*)ah, (uint2*)al, n4);
        n4 = EMBD * EMBD / 4;
        split_bf16x4<<<(n4 + 255) / 256, 256>>>((const float4*)W_out, (uint2*)woh, (uint2*)wol, n4);
    }
    // 5) Output projection (tensor cores)
    {
        dim3 grid(EMBD / GBN, M / GBM);
        gemm_bf16x3<<<grid, 256, SMEM_GEMM>>>(ah, al, woh, wol, b_out, out, M, EMBD, EMBD);
    }
}

// round 5
// speedup vs baseline: 3.3889x; 2.5495x over previous
#include <cuda_runtime.h>
#include <cuda_bf16.h>

// Problem constants
#define BATCH 4
#define SEQ   2048
#define EMBD  1024
#define NHEAD 16
#define HDIM  64
#define QKV_N (3*EMBD)

typedef __nv_bfloat16 bf16;

// ---------------------------------------------------------------------------
// Scratch (device globals: allocation-free, graph-capture safe)
// ---------------------------------------------------------------------------
__device__ __align__(256) bf16 g_xh[(size_t)BATCH * SEQ * EMBD];
__device__ __align__(256) bf16 g_xl[(size_t)BATCH * SEQ * EMBD];
__device__ __align__(256) bf16 g_wqh[(size_t)EMBD * QKV_N];
__device__ __align__(256) bf16 g_wql[(size_t)EMBD * QKV_N];
__device__ __align__(256) bf16 g_woh[(size_t)EMBD * EMBD];
__device__ __align__(256) bf16 g_wol[(size_t)EMBD * EMBD];
__device__ __align__(256) bf16 g_qkvh[(size_t)BATCH * SEQ * QKV_N];
__device__ __align__(256) bf16 g_qkvl[(size_t)BATCH * SEQ * QKV_N];
__device__ __align__(256) bf16 g_ah[(size_t)BATCH * SEQ * EMBD];
__device__ __align__(256) bf16 g_al[(size_t)BATCH * SEQ * EMBD];

// ---------------------------------------------------------------------------
// Common PTX helpers
// ---------------------------------------------------------------------------
__device__ __forceinline__ unsigned sptr(const void* p) {
    return (unsigned)__cvta_generic_to_shared(p);
}
__device__ __forceinline__ void cpa16(unsigned s, const void* g) {
    asm volatile("cp.async.cg.shared.global [%0], [%1], 16;\n" :: "r"(s), "l"(g));
}
__device__ __forceinline__ void ldsm4(unsigned* r, unsigned a) {
    asm volatile("ldmatrix.sync.aligned.m8n8.x4.shared.b16 {%0,%1,%2,%3},[%4];"
                 : "=r"(r[0]), "=r"(r[1]), "=r"(r[2]), "=r"(r[3]) : "r"(a));
}
__device__ __forceinline__ void ldsm4t(unsigned* r, unsigned a) {
    asm volatile("ldmatrix.sync.aligned.m8n8.x4.trans.shared.b16 {%0,%1,%2,%3},[%4];"
                 : "=r"(r[0]), "=r"(r[1]), "=r"(r[2]), "=r"(r[3]) : "r"(a));
}
__device__ __forceinline__ void mma16816(float* d, const unsigned* a, const unsigned* b) {
    asm volatile(
        "mma.sync.aligned.m16n8k16.row.col.f32.bf16.bf16.f32 "
        "{%0,%1,%2,%3},{%4,%5,%6,%7},{%8,%9},{%0,%1,%2,%3};"
        : "+f"(d[0]), "+f"(d[1]), "+f"(d[2]), "+f"(d[3])
        : "r"(a[0]), "r"(a[1]), "r"(a[2]), "r"(a[3]), "r"(b[0]), "r"(b[1]));
}
// split fp32 pair -> packed bf16x2 hi + lo
__device__ __forceinline__ void split2(float a, float b, unsigned& h, unsigned& l) {
    bf16 ah = __float2bfloat16_rn(a);
    bf16 bh = __float2bfloat16_rn(b);
    bf16 al = __float2bfloat16_rn(a - __bfloat162float(ah));
    bf16 bl = __float2bfloat16_rn(b - __bfloat162float(bh));
    h = (unsigned)__bfloat16_as_ushort(ah) | ((unsigned)__bfloat16_as_ushort(bh) << 16);
    l = (unsigned)__bfloat16_as_ushort(al) | ((unsigned)__bfloat16_as_ushort(bl) << 16);
}

// ---------------------------------------------------------------------------
// fp32 -> (bf16 hi, bf16 lo) split, vectorized x4 (inputs only)
// ---------------------------------------------------------------------------
__global__ __launch_bounds__(256) void split_bf16x4(
    const float4* __restrict__ in, uint2* __restrict__ hi, uint2* __restrict__ lo, int n4)
{
    int i = blockIdx.x * blockDim.x + threadIdx.x;
    if (i >= n4) return;
    float4 v = in[i];
    uint2 ho, loo;
    split2(v.x, v.y, ho.x, loo.x);
    split2(v.z, v.w, ho.y, loo.y);
    hi[i] = ho;
    lo[i] = loo;
}

// ---------------------------------------------------------------------------
// Tensor-core GEMM, bf16x3 emulated fp32: C = Ah@Bh + Ah@Bl + Al@Bh + bias
// OMODE 0: write fp32 C.   OMODE 1: write bf16 hi/lo split of C.
// ---------------------------------------------------------------------------
#define GBM 128
#define GBN 128
#define GBK 32
#define APITCH 40
#define BPITCH 136
#define ASZ (128*APITCH)
#define BSZ (32*BPITCH)

template<int OMODE>
__global__ __launch_bounds__(256, 1) void gemm_bf16x3(
    const bf16* __restrict__ Agh, const bf16* __restrict__ Agl,
    const bf16* __restrict__ Bgh, const bf16* __restrict__ Bgl,
    const float* __restrict__ bias,
    float* __restrict__ C, bf16* __restrict__ Ch, bf16* __restrict__ Cl,
    int M, int N, int K)
{
    extern __shared__ char smem[];
    bf16* sAh = (bf16*)smem;
    bf16* sAl = sAh + 2 * ASZ;
    bf16* sBh = sAl + 2 * ASZ;
    bf16* sBl = sBh + 2 * BSZ;

    const int tid  = threadIdx.x;
    const int lane = tid & 31;
    const int warp = tid >> 5;
    const int bm   = blockIdx.y * GBM;
    const int bn   = blockIdx.x * GBN;
    const int wm   = (warp & 1) * 64;
    const int wn   = (warp >> 1) * 32;

    float acc[4][4][4];
#pragma unroll
    for (int mi = 0; mi < 4; mi++)
#pragma unroll
        for (int n = 0; n < 4; n++)
#pragma unroll
            for (int e = 0; e < 4; e++) acc[mi][n][e] = 0.f;

    auto prefetch = [&](int st, int k0) {
        const bf16* ah = Agh + (size_t)bm * K + k0;
        const bf16* al = Agl + (size_t)bm * K + k0;
#pragma unroll
        for (int i = 0; i < 2; i++) {
            int idx = tid + i * 256;
            int r = idx >> 2, c = (idx & 3) * 8;
            cpa16(sptr(&sAh[st * ASZ + r * APITCH + c]), ah + (size_t)r * K + c);
            cpa16(sptr(&sAl[st * ASZ + r * APITCH + c]), al + (size_t)r * K + c);
        }
        const bf16* bh = Bgh + (size_t)k0 * N + bn;
        const bf16* bl = Bgl + (size_t)k0 * N + bn;
#pragma unroll
        for (int i = 0; i < 2; i++) {
            int idx = tid + i * 256;
            int r = idx >> 4, c = (idx & 15) * 8;
            cpa16(sptr(&sBh[st * BSZ + r * BPITCH + c]), bh + (size_t)r * N + c);
            cpa16(sptr(&sBl[st * BSZ + r * BPITCH + c]), bl + (size_t)r * N + c);
        }
        asm volatile("cp.async.commit_group;");
    };

    const int NIT = K / GBK;
    prefetch(0, 0);
    for (int it = 0; it < NIT; it++) {
        if (it + 1 < NIT) {
            prefetch((it + 1) & 1, (it + 1) * GBK);
            asm volatile("cp.async.wait_group 1;");
        } else {
            asm volatile("cp.async.wait_group 0;");
        }
        __syncthreads();
        const int st = it & 1;

#pragma unroll
        for (int kk = 0; kk < GBK; kk += 16) {
            unsigned ah[4][4], al[4][4], bh[2][4], bl[2][4];
#pragma unroll
            for (int mi = 0; mi < 4; mi++) {
                int row = wm + mi * 16 + (lane & 15);
                int col = kk + (lane >> 4) * 8;
                ldsm4(ah[mi], sptr(&sAh[st * ASZ + row * APITCH + col]));
                ldsm4(al[mi], sptr(&sAl[st * ASZ + row * APITCH + col]));
            }
#pragma unroll
            for (int nj = 0; nj < 2; nj++) {
                int row = kk + (lane & 15);
                int col = wn + nj * 16 + (lane >> 4) * 8;
                ldsm4t(bh[nj], sptr(&sBh[st * BSZ + row * BPITCH + col]));
                ldsm4t(bl[nj], sptr(&sBl[st * BSZ + row * BPITCH + col]));
            }
#pragma unroll
            for (int mi = 0; mi < 4; mi++)
#pragma unroll
                for (int nj = 0; nj < 2; nj++)
#pragma unroll
                    for (int sub = 0; sub < 2; sub++) {
                        int n = nj * 2 + sub;
                        mma16816(acc[mi][n], ah[mi], &bh[nj][sub * 2]);
                        mma16816(acc[mi][n], ah[mi], &bl[nj][sub * 2]);
                        mma16816(acc[mi][n], al[mi], &bh[nj][sub * 2]);
                    }
        }
        __syncthreads();
    }

#pragma unroll
    for (int mi = 0; mi < 4; mi++) {
        int r0 = bm + wm + mi * 16 + (lane >> 2);
#pragma unroll
        for (int n = 0; n < 4; n++) {
            int c0 = bn + wn + n * 8 + (lane & 3) * 2;
            float2 bv = *(const float2*)(bias + c0);
            float v00 = acc[mi][n][0] + bv.x, v01 = acc[mi][n][1] + bv.y;
            float v10 = acc[mi][n][2] + bv.x, v11 = acc[mi][n][3] + bv.y;
            if (OMODE == 0) {
                *(float2*)(C + (size_t)r0 * N + c0) = make_float2(v00, v01);
                *(float2*)(C + (size_t)(r0 + 8) * N + c0) = make_float2(v10, v11);
            } else {
                unsigned h0, l0, h1, l1;
                split2(v00, v01, h0, l0);
                split2(v10, v11, h1, l1);
                *(unsigned*)(Ch + (size_t)r0 * N + c0) = h0;
                *(unsigned*)(Cl + (size_t)r0 * N + c0) = l0;
                *(unsigned*)(Ch + (size_t)(r0 + 8) * N + c0) = h1;
                *(unsigned*)(Cl + (size_t)(r0 + 8) * N + c0) = l1;
            }
        }
    }
}

// ---------------------------------------------------------------------------
// Tensor-core causal flash attention.
// CTA: 256 threads (8 warps), q-tile 128 rows of one (b,h); warp w owns 16 rows.
// K/V tiles of 64 rows, bf16 hi/lo, cp.async double buffered.
// QK^T: Qh*Kh + Qh*Kl + Ql*Kh.  PV: Ph*Vh + Ph*Vl + Pl*Vh.
// Output written as bf16 hi/lo for the out-projection GEMM.
// ---------------------------------------------------------------------------
#define KP 72                      // smem pitch (64 + 8 pad)
#define TSZ (64*KP)                // one tensor tile
#define STG (4*TSZ)                // tensors per stage: Kh,Kl,Vh,Vl
#define FLASH_SMEM (2*STG*2)       // bytes

__global__ __launch_bounds__(256, 1) void flash_attn_mma(
    const bf16* __restrict__ qvh, const bf16* __restrict__ qvl,
    bf16* __restrict__ outh, bf16* __restrict__ outl)
{
    extern __shared__ char smraw[];
    bf16* sm = (bf16*)smraw;

    const int tid  = threadIdx.x;
    const int lane = tid & 31;
    const int warp = tid >> 5;
    const int bh   = blockIdx.y;
    const int b    = bh >> 4;
    const int h    = bh & (NHEAD - 1);
    const int qb   = (gridDim.x - 1) - blockIdx.x;  // heavy tiles first
    const int q0   = qb * 128;
    const int wm   = warp * 16;
    const int r    = lane >> 2;                     // 0..7
    const int cp   = (lane & 3) * 2;
    const int qrow = q0 + wm + r;                   // rows r / r+8

    // ---- Q fragments straight from global (packed bf16x2 = one u32) ----
    unsigned qfh[4][4], qfl[4][4];
    {
        const size_t base  = ((size_t)(b * SEQ) + qrow) * QKV_N + h * HDIM;
        const size_t base8 = base + (size_t)8 * QKV_N;
#pragma unroll
        for (int kk = 0; kk < 4; kk++) {
            int c0 = kk * 16 + cp;
            qfh[kk][0] = *(const unsigned*)(qvh + base  + c0);
            qfh[kk][1] = *(const unsigned*)(qvh + base8 + c0);
            qfh[kk][2] = *(const unsigned*)(qvh + base  + c0 + 8);
            qfh[kk][3] = *(const unsigned*)(qvh + base8 + c0 + 8);
            qfl[kk][0] = *(const unsigned*)(qvl + base  + c0);
            qfl[kk][1] = *(const unsigned*)(qvl + base8 + c0);
            qfl[kk][2] = *(const unsigned*)(qvl + base  + c0 + 8);
            qfl[kk][3] = *(const unsigned*)(qvl + base8 + c0 + 8);
        }
    }

    float m0 = -1e30f, m1 = -1e30f, l0 = 0.f, l1 = 0.f;
    float o[8][4];
#pragma unroll
    for (int nf = 0; nf < 8; nf++)
#pragma unroll
        for (int e = 0; e < 4; e++) o[nf][e] = 0.f;

    const size_t koff = (size_t)EMBD + h * HDIM;
    const size_t voff = (size_t)(2 * EMBD) + h * HDIM;

    auto prefetch = [&](int st, int k0) {
#pragma unroll
        for (int i = 0; i < 8; i++) {
            int id = tid + i * 256;
            int t  = id >> 9;                 // 0..3 : Kh,Kl,Vh,Vl
            int rr = (id >> 3) & 63;
            int cc = (id & 7) * 8;
            const bf16* src = ((t & 1) ? qvl : qvh)
                            + ((size_t)(b * SEQ) + k0 + rr) * QKV_N
                            + ((t >= 2) ? voff : koff) + cc;
            cpa16(sptr(&sm[st * STG + t * TSZ + rr * KP + cc]), src);
        }
        asm volatile("cp.async.commit_group;");
    };

    const int ntiles = 2 * qb + 2;
    prefetch(0, 0);
    for (int t = 0; t < ntiles; t++) {
        const int k0 = t * 64;
        if (t + 1 < ntiles) {
            prefetch((t + 1) & 1, (t + 1) * 64);
            asm volatile("cp.async.wait_group 1;");
        } else {
            asm volatile("cp.async.wait_group 0;");
        }
        __syncthreads();
        const int st = t & 1;

        if (k0 <= q0 + wm + 15) {   // causal warp-level skip
            const bf16* Kh = sm + st * STG + 0 * TSZ;
            const bf16* Kl = sm + st * STG + 1 * TSZ;
            const bf16* Vh = sm + st * STG + 2 * TSZ;
            const bf16* Vl = sm + st * STG + 3 * TSZ;

            // ---- S = Q K^T ----
            float s[8][4];
#pragma unroll
            for (int nf = 0; nf < 8; nf++)
#pragma unroll
                for (int e = 0; e < 4; e++) s[nf][e] = 0.f;

#pragma unroll
            for (int kk = 0; kk < 4; kk++) {
#pragma unroll
                for (int g = 0; g < 4; g++) {
                    unsigned kh4[4], kl4[4];
                    int off = (16 * g + (lane & 15)) * KP + kk * 16 + (lane >> 4) * 8;
                    ldsm4(kh4, sptr(Kh + off));
                    ldsm4(kl4, sptr(Kl + off));
                    unsigned b0h[2] = {kh4[0], kh4[2]}, b1h[2] = {kh4[1], kh4[3]};
                    unsigned b0l[2] = {kl4[0], kl4[2]}, b1l[2] = {kl4[1], kl4[3]};
                    mma16816(s[2*g],   qfh[kk], b0h);
                    mma16816(s[2*g],   qfh[kk], b0l);
                    mma16816(s[2*g],   qfl[kk], b0h);
                    mma16816(s[2*g+1], qfh[kk], b1h);
                    mma16816(s[2*g+1], qfh[kk], b1l);
                    mma16816(s[2*g+1], qfl[kk], b1h);
                }
            }

            // ---- masking + online softmax ----
            const bool need_mask = (k0 + 63) > (q0 + wm);
            float mx0 = -1e30f, mx1 = -1e30f;
#pragma unroll
            for (int nf = 0; nf < 8; nf++) {
#pragma unroll
                for (int e = 0; e < 4; e++) s[nf][e] *= 0.125f;
                if (need_mask) {
                    int c0 = k0 + nf * 8 + cp;
                    if (c0     > qrow)     s[nf][0] = -1e30f;
                    if (c0 + 1 > qrow)     s[nf][1] = -1e30f;
                    if (c0     > qrow + 8) s[nf][2] = -1e30f;
                    if (c0 + 1 > qrow + 8) s[nf][3] = -1e30f;
                }
                mx0 = fmaxf(mx0, fmaxf(s[nf][0], s[nf][1]));
                mx1 = fmaxf(mx1, fmaxf(s[nf][2], s[nf][3]));
            }
            mx0 = fmaxf(mx0, __shfl_xor_sync(0xffffffffu, mx0, 1));
            mx0 = fmaxf(mx0, __shfl_xor_sync(0xffffffffu, mx0, 2));
            mx1 = fmaxf(mx1, __shfl_xor_sync(0xffffffffu, mx1, 1));
            mx1 = fmaxf(mx1, __shfl_xor_sync(0xffffffffu, mx1, 2));

            const float nm0 = fmaxf(m0, mx0), nm1 = fmaxf(m1, mx1);
            const float cr0 = __expf(m0 - nm0), cr1 = __expf(m1 - nm1);
            m0 = nm0; m1 = nm1;
            l0 *= cr0; l1 *= cr1;
#pragma unroll
            for (int nf = 0; nf < 8; nf++) {
                o[nf][0] *= cr0; o[nf][1] *= cr0;
                o[nf][2] *= cr1; o[nf][3] *= cr1;
            }

            unsigned ph[8][2], pl[8][2];
#pragma unroll
            for (int nf = 0; nf < 8; nf++) {
                float p0 = __expf(s[nf][0] - m0);
                float p1 = __expf(s[nf][1] - m0);
                float p2 = __expf(s[nf][2] - m1);
                float p3 = __expf(s[nf][3] - m1);
                l0 += p0 + p1;
                l1 += p2 + p3;
                split2(p0, p1, ph[nf][0], pl[nf][0]);
                split2(p2, p3, ph[nf][1], pl[nf][1]);
            }

            // ---- O += P V ----
#pragma unroll
            for (int kp = 0; kp < 4; kp++) {
                unsigned pah[4] = {ph[2*kp][0], ph[2*kp][1], ph[2*kp+1][0], ph[2*kp+1][1]};
                unsigned pal[4] = {pl[2*kp][0], pl[2*kp][1], pl[2*kp+1][0], pl[2*kp+1][1]};
#pragma unroll
                for (int dg = 0; dg < 4; dg++) {
                    unsigned vh4[4], vl4[4];
                    int off = (kp * 16 + (lane & 15)) * KP + dg * 16 + (lane >> 4) * 8;
                    ldsm4t(vh4, sptr(Vh + off));
                    ldsm4t(vl4, sptr(Vl + off));
                    mma16816(o[2*dg],   pah, &vh4[0]);
                    mma16816(o[2*dg],   pah, &vl4[0]);
                    mma16816(o[2*dg],   pal, &vh4[0]);
                    mma16816(o[2*dg+1], pah, &vh4[2]);
                    mma16816(o[2*dg+1], pah, &vl4[2]);
                    mma16816(o[2*dg+1], pal, &vh4[2]);
                }
            }
        }
        __syncthreads();
    }

    // ---- finalize: quad-reduce l, normalize, split to bf16 hi/lo, store ----
    l0 += __shfl_xor_sync(0xffffffffu, l0, 1);
    l0 += __shfl_xor_sync(0xffffffffu, l0, 2);
    l1 += __shfl_xor_sync(0xffffffffu, l1, 1);
    l1 += __shfl_xor_sync(0xffffffffu, l1, 2);
    const float inv0 = 1.f / l0, inv1 = 1.f / l1;

    const size_t obase  = ((size_t)(b * SEQ) + qrow) * EMBD + h * HDIM;
    const size_t obase8 = obase + (size_t)8 * EMBD;
#pragma unroll
    for (int nf = 0; nf < 8; nf++) {
        int c0 = nf * 8 + cp;
        unsigned h0, lo0, h1, lo1;
        split2(o[nf][0] * inv0, o[nf][1] * inv0, h0, lo0);
        split2(o[nf][2] * inv1, o[nf][3] * inv1, h1, lo1);
        *(unsigned*)(outh + obase  + c0) = h0;
        *(unsigned*)(outl + obase  + c0) = lo0;
        *(unsigned*)(outh + obase8 + c0) = h1;
        *(unsigned*)(outl + obase8 + c0) = lo1;
    }
}

// ---------------------------------------------------------------------------
// Launch
// ---------------------------------------------------------------------------
extern "C" void kernel_launch(void* const* d_in, const int* in_sizes, int n_in,
                              void* d_out, int out_size)
{
    const float* x     = (const float*)d_in[0];
    const float* W_qkv = (const float*)d_in[1];
    const float* b_qkv = (const float*)d_in[2];
    const float* W_out = (const float*)d_in[3];
    const float* b_out = (const float*)d_in[4];
    float* out = (float*)d_out;

    bf16 *xh, *xl, *wqh, *wql, *woh, *wol, *qkvh, *qkvl, *ah, *al;
    cudaGetSymbolAddress((void**)&xh,   g_xh);
    cudaGetSymbolAddress((void**)&xl,   g_xl);
    cudaGetSymbolAddress((void**)&wqh,  g_wqh);
    cudaGetSymbolAddress((void**)&wql,  g_wql);
    cudaGetSymbolAddress((void**)&woh,  g_woh);
    cudaGetSymbolAddress((void**)&wol,  g_wol);
    cudaGetSymbolAddress((void**)&qkvh, g_qkvh);
    cudaGetSymbolAddress((void**)&qkvl, g_qkvl);
    cudaGetSymbolAddress((void**)&ah,   g_ah);
    cudaGetSymbolAddress((void**)&al,   g_al);

    const int M = BATCH * SEQ;                       // 8192
    const int SMEM_GEMM = (4*ASZ + 4*BSZ) * (int)sizeof(bf16);   // 75776
    cudaFuncSetAttribute(gemm_bf16x3<0>, cudaFuncAttributeMaxDynamicSharedMemorySize, SMEM_GEMM);
    cudaFuncSetAttribute(gemm_bf16x3<1>, cudaFuncAttributeMaxDynamicSharedMemorySize, SMEM_GEMM);
    cudaFuncSetAttribute(flash_attn_mma, cudaFuncAttributeMaxDynamicSharedMemorySize, FLASH_SMEM);

    // 1) split inputs into bf16 hi/lo
    {
        int n4 = M * EMBD / 4;
        split_bf16x4<<<(n4 + 255) / 256, 256>>>((const float4*)x, (uint2*)xh, (uint2*)xl, n4);
        n4 = EMBD * QKV_N / 4;
        split_bf16x4<<<(n4 + 255) / 256, 256>>>((const float4*)W_qkv, (uint2*)wqh, (uint2*)wql, n4);
        n4 = EMBD * EMBD / 4;
        split_bf16x4<<<(n4 + 255) / 256, 256>>>((const float4*)W_out, (uint2*)woh, (uint2*)wol, n4);
    }
    // 2) QKV projection -> bf16 hi/lo qkv directly
    {
        dim3 grid(QKV_N / GBN, M / GBM);
        gemm_bf16x3<1><<<grid, 256, SMEM_GEMM>>>(xh, xl, wqh, wql, b_qkv,
                                                 nullptr, qkvh, qkvl, M, QKV_N, EMBD);
    }
    // 3) Tensor-core flash attention -> bf16 hi/lo attn output
    {
        dim3 grid(SEQ / 128, BATCH * NHEAD);
        flash_attn_mma<<<grid, 256, FLASH_SMEM>>>(qkvh, qkvl, ah, al);
    }
    // 4) Output projection -> fp32 result
    {
        dim3 grid(EMBD / GBN, M / GBM);
        gemm_bf16x3<0><<<grid, 256, SMEM_GEMM>>>(ah, al, woh, wol, b_out,
                                                 out, nullptr, nullptr, M, EMBD, EMBD);
    }
}